// round 14
// baseline (speedup 1.0000x reference)
#include <cuda_runtime.h>
#include <cuda_bf16.h>
#include <math.h>

// Problem constants (fixed dataset): B=4096, S=32, d=512, g=512, H=2, hd=256
#define BMAX 4096
#define DMODEL 512
#define SNEIGH 32
#define QSCALE 0.0625f   // hd^-0.5

// Scratch (static device arrays; no allocation allowed)
__device__ __align__(16) __nv_bfloat16 g_Nh[1024 * 512];  // fused r-weights hi
__device__ __align__(16) __nv_bfloat16 g_Nl[1024 * 512];  // fused r-weights lo
__device__ __align__(16) __nv_bfloat16 g_Mh[512 * 1024];  // fused out-weights hi
__device__ __align__(16) __nv_bfloat16 g_Ml[512 * 1024];  // fused out-weights lo
__device__ __align__(16) __nv_bfloat16 g_Sh[BMAX * DMODEL];  // source hi
__device__ __align__(16) __nv_bfloat16 g_Sl[BMAX * DMODEL];  // source lo
__device__ __align__(16) __nv_bfloat16 g_Uh[BMAX * 1024];    // u hi
__device__ __align__(16) __nv_bfloat16 g_Ul[BMAX * 1024];    // u lo
__device__ float g_rb[1024];          // bq_h @ Wk_h
__device__ float g_vqb[1024];         // Wq_h^T @ bk_h
__device__ float g_cqb[2];            // bq_h . bk_h
__device__ float g_bc[512];           // Wout @ bv + bout
__device__ float g_r[BMAX * 1024];    // r[b,h,:]
__device__ int   g_inv[BMAX];         // all-neighbors-padded flag

// ---- packed f32x2 helpers (for the small prep GEMM) ----
__device__ __forceinline__ unsigned long long pk2(float lo, float hi) {
    unsigned long long r;
    asm("mov.b64 %0, {%1, %2};" : "=l"(r) : "f"(lo), "f"(hi));
    return r;
}
__device__ __forceinline__ float2 unpk2(unsigned long long v) {
    float2 r;
    asm("mov.b64 {%0, %1}, %2;" : "=f"(r.x), "=f"(r.y) : "l"(v));
    return r;
}
#define FMA2(d, a, b) asm("fma.rn.f32x2 %0, %1, %2, %0;" : "+l"(d) : "l"(a), "l"(b))

__device__ __forceinline__ unsigned pack_bf2(__nv_bfloat16 a, __nv_bfloat16 b) {
    return ((unsigned)__bfloat16_as_ushort(b) << 16) | __bfloat16_as_ushort(a);
}

// ---- cp.async helpers ----
__device__ __forceinline__ void cp16(void* dst, const void* src) {
    unsigned d = (unsigned)__cvta_generic_to_shared(dst);
    asm volatile("cp.async.cg.shared.global [%0], [%1], 16;\n" :: "r"(d), "l"(src));
}
#define CP_COMMIT() asm volatile("cp.async.commit_group;\n")
#define CP_WAIT(n)  asm volatile("cp.async.wait_group %0;\n" :: "n"(n))

// ===========================================================================
// bf16 split-compensated tensor-core GEMM.
//   C[M,N] = A[M,K] @ W[N,K]^T  with A = Ah+Al, W = Wh+Wl (bf16 hi/lo pairs)
//   computed as Ah*Wh + Ah*Wl + Al*Wh (fp32 accum).
// CTA tile 128x64, 8 warps (4x2), warp tile 32x32, k-step 32,
// 3-stage cp.async pipeline (stage issue BEFORE compute), 2 CTAs/SM.
// Inner loop: load all fragments once, then 3 term-major mma passes so
// consecutive mma instructions target independent accumulators.
// MODE 1: C = (acc + bias[c]) * scale                       (f32 out, ldc)
// MODE 3: C = invalid[r] ? src : (acc+bias[c])*maskn[r]+src (src ld=512)
// Smem per stage: Ah/Al 128x80B + Wh/Wl 64x80B = 30720 B;  3 stages = 92160 B
// ===========================================================================
#define SROW 80          // smem row stride in bytes (32 bf16 + 8 pad)
#define A_BYTES 10240    // 128 * 80
#define W_BYTES 5120     // 64 * 80
#define STAGE 30720      // 2*A_BYTES + 2*W_BYTES
#define NSTAGES 3

__device__ __forceinline__ void mma_bf16_(float* c,
    unsigned a0, unsigned a1, unsigned a2, unsigned a3,
    unsigned b0, unsigned b1)
{
    asm volatile(
        "mma.sync.aligned.m16n8k16.row.col.f32.bf16.bf16.f32 "
        "{%0,%1,%2,%3}, {%4,%5,%6,%7}, {%8,%9}, {%0,%1,%2,%3};\n"
        : "+f"(c[0]), "+f"(c[1]), "+f"(c[2]), "+f"(c[3])
        : "r"(a0), "r"(a1), "r"(a2), "r"(a3), "r"(b0), "r"(b1));
}

template <int MODE>
__global__ __launch_bounds__(256, 2) void mma_gemm(
    const __nv_bfloat16* __restrict__ Ah, const __nv_bfloat16* __restrict__ Al,
    const __nv_bfloat16* __restrict__ Wh, const __nv_bfloat16* __restrict__ Wl,
    float* __restrict__ C, int ldc, int K,
    const float* __restrict__ bias, float scale,
    const float* __restrict__ maskn,
    const int* __restrict__ invalid,
    const float* __restrict__ src)
{
    extern __shared__ char sm[];
    const int tid = threadIdx.x;
    const int wid = tid >> 5;
    const int lane = tid & 31;
    const int bm = blockIdx.y * 128;
    const int bn = blockIdx.x * 64;
    const int wm = (wid >> 1) * 32;   // 0,32,64,96
    const int wn = (wid & 1) * 32;    // 0,32

    // ---- cp.async fetch mapping: 6 x 16B chunks per thread per stage ----
    const int fr = tid >> 2;          // 0..63
    const int fq = tid & 3;           // 16B chunk within 64B row
    const size_t oA0 = (size_t)(bm + fr) * K + fq * 8;
    const size_t oA1 = (size_t)(bm + fr + 64) * K + fq * 8;
    const size_t oW  = (size_t)(bn + fr) * K + fq * 8;
    const int sA0 = fr * SROW + fq * 16;        // 16B-aligned (80 = 5*16)
    const int sA1 = (fr + 64) * SROW + fq * 16;
    const int sW  = fr * SROW + fq * 16;

    auto issue = [&](int s, int k0) {
        char* b = sm + s * STAGE;
        cp16(b + sA0,                        Ah + oA0 + k0);
        cp16(b + sA1,                        Ah + oA1 + k0);
        cp16(b + A_BYTES + sA0,              Al + oA0 + k0);
        cp16(b + A_BYTES + sA1,              Al + oA1 + k0);
        cp16(b + 2 * A_BYTES + sW,           Wh + oW + k0);
        cp16(b + 2 * A_BYTES + W_BYTES + sW, Wl + oW + k0);
    };

    float acc[2][4][4];
#pragma unroll
    for (int i = 0; i < 2; i++)
#pragma unroll
        for (int j = 0; j < 4; j++)
#pragma unroll
            for (int e = 0; e < 4; e++) acc[i][j][e] = 0.f;

    const int kb0 = (lane & 3) * 4;   // byte offset of this thread's k pair
    const int gidr = lane >> 2;       // fragment row/col group

    auto compute = [&](int buf) {
        const char* bA  = sm + buf * STAGE;
        const char* bAl = bA + A_BYTES;
        const char* bW  = bA + 2 * A_BYTES;
        const char* bWl = bW + W_BYTES;
#pragma unroll
        for (int ksub = 0; ksub < 2; ksub++) {
            const int kb = ksub * 32 + kb0;

            // ---- load ALL fragments for this k-substep ----
            unsigned bh[4][2], bl[4][2];
#pragma unroll
            for (int nf = 0; nf < 4; nf++) {
                const int off = (wn + nf * 8 + gidr) * SROW + kb;
                bh[nf][0] = *(const unsigned*)(bW + off);
                bh[nf][1] = *(const unsigned*)(bW + off + 16);
                bl[nf][0] = *(const unsigned*)(bWl + off);
                bl[nf][1] = *(const unsigned*)(bWl + off + 16);
            }
            unsigned ah[2][4], al[2][4];
#pragma unroll
            for (int mf = 0; mf < 2; mf++) {
                const int off = (wm + mf * 16 + gidr) * SROW + kb;
                ah[mf][0] = *(const unsigned*)(bA + off);
                ah[mf][1] = *(const unsigned*)(bA + off + 8 * SROW);
                ah[mf][2] = *(const unsigned*)(bA + off + 16);
                ah[mf][3] = *(const unsigned*)(bA + off + 8 * SROW + 16);
                al[mf][0] = *(const unsigned*)(bAl + off);
                al[mf][1] = *(const unsigned*)(bAl + off + 8 * SROW);
                al[mf][2] = *(const unsigned*)(bAl + off + 16);
                al[mf][3] = *(const unsigned*)(bAl + off + 8 * SROW + 16);
            }

            // ---- 3 term-major passes: consecutive mmas hit distinct accs ----
#pragma unroll
            for (int mf = 0; mf < 2; mf++)
#pragma unroll
                for (int nf = 0; nf < 4; nf++)
                    mma_bf16_(acc[mf][nf], ah[mf][0], ah[mf][1], ah[mf][2], ah[mf][3],
                              bh[nf][0], bh[nf][1]);
#pragma unroll
            for (int mf = 0; mf < 2; mf++)
#pragma unroll
                for (int nf = 0; nf < 4; nf++)
                    mma_bf16_(acc[mf][nf], ah[mf][0], ah[mf][1], ah[mf][2], ah[mf][3],
                              bl[nf][0], bl[nf][1]);
#pragma unroll
            for (int mf = 0; mf < 2; mf++)
#pragma unroll
                for (int nf = 0; nf < 4; nf++)
                    mma_bf16_(acc[mf][nf], al[mf][0], al[mf][1], al[mf][2], al[mf][3],
                              bh[nf][0], bh[nf][1]);
        }
    };

    // ---- 3-stage pipeline, stage issue before compute ----
    const int nk = K / 32;
    issue(0, 0);  CP_COMMIT();
    issue(1, 32); CP_COMMIT();

    int buf = 0;
    for (int k = 0; k < nk; k++) {
        CP_WAIT(1);
        __syncthreads();
        if (k + 2 < nk) issue((k + 2) % NSTAGES, (k + 2) * 32);
        CP_COMMIT();
        compute(buf);
        buf = (buf + 1) % NSTAGES;
    }

    // ---- epilogue ----
#pragma unroll
    for (int mf = 0; mf < 2; mf++) {
#pragma unroll
        for (int half = 0; half < 2; half++) {
            const int row = bm + wm + mf * 16 + gidr + half * 8;
            float mn = 0.f;
            int iv = 0;
            if (MODE == 3) { iv = invalid[row]; mn = maskn[row]; }
#pragma unroll
            for (int nf = 0; nf < 4; nf++) {
                const int col = bn + wn + nf * 8 + 2 * (lane & 3);
                float v0 = acc[mf][nf][half * 2 + 0];
                float v1 = acc[mf][nf][half * 2 + 1];
                if (MODE == 1) {
                    v0 = (v0 + bias[col]) * scale;
                    v1 = (v1 + bias[col + 1]) * scale;
                } else {
                    v0 += bias[col];
                    v1 += bias[col + 1];
                    const float* sr = src + (size_t)row * DMODEL + col;
                    v0 = iv ? sr[0] : fmaf(v0, mn, sr[0]);
                    v1 = iv ? sr[1] : fmaf(v1, mn, sr[1]);
                }
                *(float2*)&C[(size_t)row * ldc + col] = make_float2(v0, v1);
            }
        }
    }
}

// ---------------------------------------------------------------------------
// 128x128x8 SGEMM body (f32, FFMA2) for the small prep GEMMs, epilogue writes
// bf16 hi/lo pairs.  AT as before.
// ---------------------------------------------------------------------------
template <bool AT>
__device__ __forceinline__ void gemm_body_bf(
    const float* __restrict__ A, int lda,
    const float* __restrict__ W, int ldw,
    __nv_bfloat16* __restrict__ Chi, __nv_bfloat16* __restrict__ Clo,
    int ldc, int K, int bm, int bn,
    float (*As)[8][128], float (*Ws)[8][128])
{
    const int tid = threadIdx.x;
    const int arow = tid >> 1;
    const int acol = (tid & 1) << 2;
    const int wr = tid >> 5;
    const int wc = (tid & 31) << 2;
    const int ty = tid >> 4;
    const int tx = tid & 15;

    const float* Ap = AT ? (A + (size_t)wr * lda + bm + wc)
                         : (A + (size_t)(bm + arow) * lda + acol);
    const float* Wp = W + (size_t)wr * ldw + bn + wc;

    float4 av = *(const float4*)Ap;
    float4 wv = *(const float4*)Wp;
    if (AT) {
        *(float4*)&As[0][wr][wc] = av;
    } else {
        As[0][acol + 0][arow] = av.x; As[0][acol + 1][arow] = av.y;
        As[0][acol + 2][arow] = av.z; As[0][acol + 3][arow] = av.w;
    }
    *(float4*)&Ws[0][wr][wc] = wv;
    __syncthreads();

    unsigned long long acc2[8][4];
#pragma unroll
    for (int i = 0; i < 8; i++)
#pragma unroll
        for (int j = 0; j < 4; j++) acc2[i][j] = 0ull;

    int buf = 0;
    for (int k0 = 8; k0 <= K; k0 += 8) {
        const bool more = (k0 < K);
        if (more) {
            av = *(const float4*)(Ap + (AT ? (size_t)k0 * lda : (size_t)k0));
            wv = *(const float4*)(Wp + (size_t)k0 * ldw);
        }
#pragma unroll
        for (int k = 0; k < 8; k++) {
            float4 a0 = *(const float4*)&As[buf][k][ty * 8];
            float4 a1 = *(const float4*)&As[buf][k][ty * 8 + 4];
            float4 b0 = *(const float4*)&Ws[buf][k][tx * 8];
            float4 b1 = *(const float4*)&Ws[buf][k][tx * 8 + 4];
            unsigned long long rb2[4];
            rb2[0] = pk2(b0.x, b0.y); rb2[1] = pk2(b0.z, b0.w);
            rb2[2] = pk2(b1.x, b1.y); rb2[3] = pk2(b1.z, b1.w);
            float ra[8] = {a0.x, a0.y, a0.z, a0.w, a1.x, a1.y, a1.z, a1.w};
#pragma unroll
            for (int i = 0; i < 8; i++) {
                unsigned long long ra2 = pk2(ra[i], ra[i]);
#pragma unroll
                for (int j = 0; j < 4; j++) FMA2(acc2[i][j], ra2, rb2[j]);
            }
        }
        if (more) {
            const int nb = buf ^ 1;
            if (AT) {
                *(float4*)&As[nb][wr][wc] = av;
            } else {
                As[nb][acol + 0][arow] = av.x; As[nb][acol + 1][arow] = av.y;
                As[nb][acol + 2][arow] = av.z; As[nb][acol + 3][arow] = av.w;
            }
            *(float4*)&Ws[nb][wr][wc] = wv;
            __syncthreads();
            buf = nb;
        }
    }

#pragma unroll
    for (int i = 0; i < 8; i++) {
        const int r = bm + ty * 8 + i;
#pragma unroll
        for (int j = 0; j < 4; j++) {
            float2 p = unpk2(acc2[i][j]);
            float vv[2] = {p.x, p.y};
#pragma unroll
            for (int e = 0; e < 2; e++) {
                const int c = bn + tx * 8 + j * 2 + e;
                __nv_bfloat16 hi = __float2bfloat16(vv[e]);
                __nv_bfloat16 lo = __float2bfloat16(vv[e] - __bfloat162float(hi));
                Chi[(size_t)r * ldc + c] = hi;
                Clo[(size_t)r * ldc + c] = lo;
            }
        }
    }
}

// ---------------------------------------------------------------------------
// Combined prep: one launch, 135 CTAs.
//   0..31 : Ncat hi/lo (TN, K=256)    32..63 : Mcat hi/lo (NN, K=256)
//  64..65 : rb   66..67 : vqb   68..69 : bc   70 : cqb
//  71..134: source -> bf16 hi/lo
// ---------------------------------------------------------------------------
__global__ __launch_bounds__(256) void prep_all(
    const float* __restrict__ source,
    const float* __restrict__ Wq, const float* __restrict__ bq,
    const float* __restrict__ Wk, const float* __restrict__ bk,
    const float* __restrict__ Wv, const float* __restrict__ bv,
    const float* __restrict__ Wout, const float* __restrict__ bout)
{
    __shared__ float As[2][8][128];
    __shared__ float Ws[2][8][128];
    const int bid = blockIdx.x;
    const int tid = threadIdx.x;

    if (bid < 32) {
        const int h = bid >> 4, t = bid & 15;
        gemm_body_bf<true>(
            Wk + (size_t)h * 256 * DMODEL, DMODEL,
            Wq + (size_t)h * 256 * DMODEL, DMODEL,
            g_Nh + (size_t)h * 512 * DMODEL, g_Nl + (size_t)h * 512 * DMODEL,
            DMODEL, 256, (t >> 2) * 128, (t & 3) * 128, As, Ws);
    } else if (bid < 64) {
        const int idx = bid - 32, h = idx >> 4, t = idx & 15;
        gemm_body_bf<false>(
            Wout + (size_t)h * 256, DMODEL,
            Wv + (size_t)h * 256 * DMODEL, DMODEL,
            g_Mh + (size_t)h * 512, g_Ml + (size_t)h * 512,
            1024, 256, (t >> 2) * 128, (t & 3) * 128, As, Ws);
    } else if (bid < 66) {               // rb[h*512+g] = sum_j bq_h[j]*Wk_h[j,g]
        const int h = bid - 64;
        for (int cc = tid; cc < 512; cc += 256) {
            float acc = 0.f;
#pragma unroll 4
            for (int j = 0; j < 256; j++)
                acc = fmaf(bq[h * 256 + j], Wk[(size_t)(h * 256 + j) * 512 + cc], acc);
            g_rb[h * 512 + cc] = acc;
        }
    } else if (bid < 68) {               // vqb[h*512+k] = sum_j bk_h[j]*Wq_h[j,k]
        const int h = bid - 66;
        for (int cc = tid; cc < 512; cc += 256) {
            float acc = 0.f;
#pragma unroll 4
            for (int j = 0; j < 256; j++)
                acc = fmaf(bk[h * 256 + j], Wq[(size_t)(h * 256 + j) * 512 + cc], acc);
            g_vqb[h * 512 + cc] = acc;
        }
    } else if (bid < 70) {               // bc[j] = Wout[j,:].bv + bout[j]
        const int warp = tid >> 5, lane = tid & 31;
        const int base = (bid - 68) * 256;
        for (int i = 0; i < 32; i++) {
            const int j = base + warp * 32 + i;
            float s = 0.f;
            for (int c = lane; c < 512; c += 32)
                s = fmaf(Wout[(size_t)j * 512 + c], bv[c], s);
#pragma unroll
            for (int o = 16; o; o >>= 1) s += __shfl_xor_sync(0xffffffffu, s, o);
            if (lane == 0) g_bc[j] = s + bout[j];
        }
    } else if (bid == 70) {              // cqb[h] = bq_h . bk_h
        const int warp = tid >> 5, lane = tid & 31;
        if (warp < 2) {
            float s = 0.f;
            for (int j = lane; j < 256; j += 32)
                s = fmaf(bq[warp * 256 + j], bk[warp * 256 + j], s);
#pragma unroll
            for (int o = 16; o; o >>= 1) s += __shfl_xor_sync(0xffffffffu, s, o);
            if (lane == 0) g_cqb[warp] = s;
        }
    } else {                             // source -> bf16 hi/lo
        const int sb = bid - 71;         // 0..63
        const float4* sp = (const float4*)source;
        uint2* hOut = (uint2*)g_Sh;
        uint2* lOut = (uint2*)g_Sl;
#pragma unroll 4
        for (int i = 0; i < 32; i++) {
            const int idx = sb * 8192 + i * 256 + tid;
            float4 v = sp[idx];
            __nv_bfloat16 h0 = __float2bfloat16(v.x);
            __nv_bfloat16 h1 = __float2bfloat16(v.y);
            __nv_bfloat16 h2 = __float2bfloat16(v.z);
            __nv_bfloat16 h3 = __float2bfloat16(v.w);
            __nv_bfloat16 l0 = __float2bfloat16(v.x - __bfloat162float(h0));
            __nv_bfloat16 l1 = __float2bfloat16(v.y - __bfloat162float(h1));
            __nv_bfloat16 l2 = __float2bfloat16(v.z - __bfloat162float(h2));
            __nv_bfloat16 l3 = __float2bfloat16(v.w - __bfloat162float(h3));
            hOut[idx] = make_uint2(pack_bf2(h0, h1), pack_bf2(h2, h3));
            lOut[idx] = make_uint2(pack_bf2(l0, l1), pack_bf2(l2, l3));
        }
    }
}

// ---------------------------------------------------------------------------
// Per-row attention: qb, scores = r.gene + qb, mask (+slot-0 fix), softmax,
// attn_weight (head-mean), u = sum_s w*gene (written as bf16 hi/lo).
// One block per b, 256 threads.  gene cached in dynamic smem (read once).
// ---------------------------------------------------------------------------
__global__ __launch_bounds__(256) void attn_kernel(
    const float* __restrict__ gene,
    const unsigned int* __restrict__ mask,
    const float* __restrict__ source,
    float* __restrict__ aw_out)
{
    extern __shared__ float dsm[];
    float* sg = dsm;            // [32*512] gene block
    float* rs = dsm + 16384;    // [1024] r row
    __shared__ float sc[64];
    __shared__ float wgt[64];
    __shared__ float qbs[2];
    __shared__ int mk[32];

    const int b = blockIdx.x;
    const int tid = threadIdx.x;
    const int warp = tid >> 5;
    const int lane = tid & 31;
    const float* gb = gene + (size_t)b * (SNEIGH * DMODEL);

    // load gene block (64KB) + r row into smem
    {
        const float4* gp = (const float4*)gb;
        float4* sp = (float4*)sg;
#pragma unroll
        for (int i = 0; i < 16; i++) sp[tid + i * 256] = gp[tid + i * 256];
        ((float4*)rs)[tid] = ((const float4*)(g_r + (size_t)b * 1024))[tid];
    }
    if (tid < 32) mk[tid] = (mask[b * 32 + tid] != 0u) ? 1 : 0;

    // qb[h] = s*(source[b].vqb_h + cqb_h)  (warps 2,3)
    if (warp == 2 || warp == 3) {
        const int h = warp - 2;
        const float* sr = source + (size_t)b * DMODEL;
        const float* vq = g_vqb + h * 512;
        float s = 0.f;
#pragma unroll
        for (int k = lane; k < 512; k += 32) s = fmaf(sr[k], vq[k], s);
#pragma unroll
        for (int o = 16; o; o >>= 1) s += __shfl_xor_sync(0xffffffffu, s, o);
        if (lane == 0) qbs[h] = QSCALE * (s + g_cqb[h]);
    }
    __syncthreads();

    if (warp == 0) {
        unsigned ball = __ballot_sync(0xffffffffu, mk[lane] != 0);
        if (lane == 0) {
            int inv = (ball == 0xffffffffu);
            g_inv[b] = inv;
            if (inv) mk[0] = 0;   // torch in-place fix: unmask slot 0
        }
    }
    __syncthreads();

    // scores: 64 (h,s) pairs; each warp does 8 full-warp dot-512s (smem only)
    for (int p = warp; p < 64; p += 8) {
        const int h = p >> 5, s = p & 31;
        const float* gr = sg + s * DMODEL;
        const float* rr = rs + h * 512;
        float sum = 0.f;
#pragma unroll
        for (int k = lane; k < 512; k += 32) sum = fmaf(rr[k], gr[k], sum);
#pragma unroll
        for (int o = 16; o; o >>= 1) sum += __shfl_xor_sync(0xffffffffu, sum, o);
        if (lane == 0) sc[p] = sum + qbs[h];
    }
    __syncthreads();

    // softmax per head (warps 0,1; lane = s)
    if (warp < 2) {
        float v = mk[lane] ? -INFINITY : sc[warp * 32 + lane];
        float mx = v;
#pragma unroll
        for (int o = 16; o; o >>= 1) mx = fmaxf(mx, __shfl_xor_sync(0xffffffffu, mx, o));
        float e = __expf(v - mx);
        float ssum = e;
#pragma unroll
        for (int o = 16; o; o >>= 1) ssum += __shfl_xor_sync(0xffffffffu, ssum, o);
        wgt[warp * 32 + lane] = e / ssum;
    }
    __syncthreads();

    if (tid < 32) aw_out[(size_t)b * 32 + tid] = 0.5f * (wgt[tid] + wgt[32 + tid]);

    // u[b,h,:] = sum_s w[h,s] * gene[b,s,:]  (from smem), write bf16 hi/lo
    const int g = tid;  // 0..255
    float a00 = 0.f, a01 = 0.f, a10 = 0.f, a11 = 0.f;
#pragma unroll 8
    for (int s = 0; s < 32; s++) {
        const float w0 = wgt[s];
        const float w1 = wgt[32 + s];
        const float gv0 = sg[s * DMODEL + g];
        const float gv1 = sg[s * DMODEL + g + 256];
        a00 = fmaf(w0, gv0, a00);
        a01 = fmaf(w0, gv1, a01);
        a10 = fmaf(w1, gv0, a10);
        a11 = fmaf(w1, gv1, a11);
    }
    __nv_bfloat16* uh = g_Uh + (size_t)b * 1024;
    __nv_bfloat16* ul = g_Ul + (size_t)b * 1024;
    float uv[4] = {a00, a01, a10, a11};
#pragma unroll
    for (int e = 0; e < 4; e++) {
        __nv_bfloat16 hi = __float2bfloat16(uv[e]);
        __nv_bfloat16 lo = __float2bfloat16(uv[e] - __bfloat162float(hi));
        uh[e * 256 + g] = hi;
        ul[e * 256 + g] = lo;
    }
}

// ---------------------------------------------------------------------------
extern "C" void kernel_launch(void* const* d_in, const int* in_sizes, int n_in,
                              void* d_out, int out_size)
{
    const float* source = (const float*)d_in[0];
    const float* gene   = (const float*)d_in[1];
    const unsigned int* mask = (const unsigned int*)d_in[2];
    const float* mask_n = (const float*)d_in[3];
    const float* Wq = (const float*)d_in[4];
    const float* bq = (const float*)d_in[5];
    const float* Wk = (const float*)d_in[6];
    const float* bk = (const float*)d_in[7];
    const float* Wv = (const float*)d_in[8];
    const float* bv = (const float*)d_in[9];
    const float* Wout = (const float*)d_in[10];
    const float* bout = (const float*)d_in[11];

    const int B = in_sizes[0] / DMODEL;   // 4096

    float* out = (float*)d_out;                         // [B,512]
    float* aw  = (float*)d_out + (size_t)B * DMODEL;    // [B,32]

    __nv_bfloat16 *Nh, *Nl, *Mh, *Ml, *Sh, *Sl, *Uh, *Ul;
    cudaGetSymbolAddress((void**)&Nh, g_Nh);  cudaGetSymbolAddress((void**)&Nl, g_Nl);
    cudaGetSymbolAddress((void**)&Mh, g_Mh);  cudaGetSymbolAddress((void**)&Ml, g_Ml);
    cudaGetSymbolAddress((void**)&Sh, g_Sh);  cudaGetSymbolAddress((void**)&Sl, g_Sl);
    cudaGetSymbolAddress((void**)&Uh, g_Uh);  cudaGetSymbolAddress((void**)&Ul, g_Ul);
    float* rbg; cudaGetSymbolAddress((void**)&rbg, g_rb);
    float* bcg; cudaGetSymbolAddress((void**)&bcg, g_bc);
    float* rg;  cudaGetSymbolAddress((void**)&rg, g_r);
    int*   ivg; cudaGetSymbolAddress((void**)&ivg, g_inv);

    static bool attrs_set = false;
    if (!attrs_set) {
        cudaFuncSetAttribute(mma_gemm<1>, cudaFuncAttributeMaxDynamicSharedMemorySize, NSTAGES * STAGE);
        cudaFuncSetAttribute(mma_gemm<3>, cudaFuncAttributeMaxDynamicSharedMemorySize, NSTAGES * STAGE);
        cudaFuncSetAttribute(attn_kernel, cudaFuncAttributeMaxDynamicSharedMemorySize, 17408 * 4);
        attrs_set = true;
    }

    // P) fused weights (bf16 hi/lo) + bias vectors + source conversion
    prep_all<<<135, 256>>>(source, Wq, bq, Wk, bk, Wv, bv, Wout, bout);

    // 1) r = QSCALE * (source @ Ncat^T + rb)   [B,1024], K=512  (tensor cores)
    mma_gemm<1><<<dim3(1024 / 64, B / 128), 256, NSTAGES * STAGE>>>(
        Sh, Sl, Nh, Nl, rg, 1024, DMODEL,
        rbg, QSCALE, nullptr, nullptr, nullptr);

    // 2) per-row attention: qb, scores, mask fix, softmax, attn_weight, u
    attn_kernel<<<B, 256, 17408 * 4>>>(gene, mask, source, aw);

    // 3) out = invalid ? source : (u @ Mcat^T + bc) * mask_n + source  K=1024
    mma_gemm<3><<<dim3(DMODEL / 64, B / 128), 256, NSTAGES * STAGE>>>(
        Uh, Ul, Mh, Ml, out, DMODEL, 1024,
        bcg, 1.f, mask_n, ivg, source);
}

// round 15
// speedup vs baseline: 1.0989x; 1.0989x over previous
#include <cuda_runtime.h>
#include <cuda_bf16.h>
#include <math.h>

// Problem constants (fixed dataset): B=4096, S=32, d=512, g=512, H=2, hd=256
#define BMAX 4096
#define DMODEL 512
#define SNEIGH 32
#define QSCALE 0.0625f   // hd^-0.5

// Scratch (static device arrays; no allocation allowed)
__device__ __align__(16) __nv_bfloat16 g_Nh[1024 * 512];  // fused r-weights hi
__device__ __align__(16) __nv_bfloat16 g_Nl[1024 * 512];  // fused r-weights lo
__device__ __align__(16) __nv_bfloat16 g_Mh[512 * 1024];  // fused out-weights hi
__device__ __align__(16) __nv_bfloat16 g_Ml[512 * 1024];  // fused out-weights lo
__device__ __align__(16) __nv_bfloat16 g_Sh[BMAX * DMODEL];  // source hi
__device__ __align__(16) __nv_bfloat16 g_Sl[BMAX * DMODEL];  // source lo
__device__ __align__(16) __nv_bfloat16 g_Uh[BMAX * 1024];    // u hi
__device__ __align__(16) __nv_bfloat16 g_Ul[BMAX * 1024];    // u lo
__device__ float g_rb[1024];          // bq_h @ Wk_h
__device__ float g_vqb[1024];         // Wq_h^T @ bk_h
__device__ float g_cqb[2];            // bq_h . bk_h
__device__ float g_bc[512];           // Wout @ bv + bout
__device__ float g_r[BMAX * 1024];    // r[b,h,:]
__device__ int   g_inv[BMAX];         // all-neighbors-padded flag

// ---- packed f32x2 helpers (for the small prep GEMM) ----
__device__ __forceinline__ unsigned long long pk2(float lo, float hi) {
    unsigned long long r;
    asm("mov.b64 %0, {%1, %2};" : "=l"(r) : "f"(lo), "f"(hi));
    return r;
}
__device__ __forceinline__ float2 unpk2(unsigned long long v) {
    float2 r;
    asm("mov.b64 {%0, %1}, %2;" : "=f"(r.x), "=f"(r.y) : "l"(v));
    return r;
}
#define FMA2(d, a, b) asm("fma.rn.f32x2 %0, %1, %2, %0;" : "+l"(d) : "l"(a), "l"(b))

__device__ __forceinline__ unsigned pack_bf2(__nv_bfloat16 a, __nv_bfloat16 b) {
    return ((unsigned)__bfloat16_as_ushort(b) << 16) | __bfloat16_as_ushort(a);
}

// ---- cp.async helpers ----
__device__ __forceinline__ void cp16(void* dst, const void* src) {
    unsigned d = (unsigned)__cvta_generic_to_shared(dst);
    asm volatile("cp.async.cg.shared.global [%0], [%1], 16;\n" :: "r"(d), "l"(src));
}
#define CP_COMMIT() asm volatile("cp.async.commit_group;\n")
#define CP_WAIT(n)  asm volatile("cp.async.wait_group %0;\n" :: "n"(n))

// ===========================================================================
// bf16 split-compensated tensor-core GEMM.
//   C[M,N] = A[M,K] @ W[N,K]^T  with A = Ah+Al, W = Wh+Wl (bf16 hi/lo pairs)
//   computed as Ah*Wh + Ah*Wl + Al*Wh (fp32 accum).
// CTA tile 128x64, 8 warps (4x2), warp tile 32x32, k-step 32,
// 3-stage cp.async pipeline, 2 CTAs/SM.  (R11 mainloop — proven fastest.)
// MODE 1: C = (acc + bias[c]) * scale                       (f32 out, ldc)
// MODE 3: C = invalid[r] ? src : (acc+bias[c])*maskn[r]+src (src ld=512)
// Smem per stage: Ah/Al 128x80B + Wh/Wl 64x80B = 30720 B;  3 stages = 92160 B
// ===========================================================================
#define SROW 80          // smem row stride in bytes (32 bf16 + 8 pad)
#define A_BYTES 10240    // 128 * 80
#define W_BYTES 5120     // 64 * 80
#define STAGE 30720      // 2*A_BYTES + 2*W_BYTES
#define NSTAGES 3

__device__ __forceinline__ void mma_bf16_(float* c,
    unsigned a0, unsigned a1, unsigned a2, unsigned a3,
    unsigned b0, unsigned b1)
{
    asm volatile(
        "mma.sync.aligned.m16n8k16.row.col.f32.bf16.bf16.f32 "
        "{%0,%1,%2,%3}, {%4,%5,%6,%7}, {%8,%9}, {%0,%1,%2,%3};\n"
        : "+f"(c[0]), "+f"(c[1]), "+f"(c[2]), "+f"(c[3])
        : "r"(a0), "r"(a1), "r"(a2), "r"(a3), "r"(b0), "r"(b1));
}

template <int MODE>
__global__ __launch_bounds__(256, 2) void mma_gemm(
    const __nv_bfloat16* __restrict__ Ah, const __nv_bfloat16* __restrict__ Al,
    const __nv_bfloat16* __restrict__ Wh, const __nv_bfloat16* __restrict__ Wl,
    float* __restrict__ C, int ldc, int K,
    const float* __restrict__ bias, float scale,
    const float* __restrict__ maskn,
    const int* __restrict__ invalid,
    const float* __restrict__ src)
{
    extern __shared__ char sm[];
    const int tid = threadIdx.x;
    const int wid = tid >> 5;
    const int lane = tid & 31;
    const int bm = blockIdx.y * 128;
    const int bn = blockIdx.x * 64;
    const int wm = (wid >> 1) * 32;   // 0,32,64,96
    const int wn = (wid & 1) * 32;    // 0,32

    // ---- cp.async fetch mapping: 6 x 16B chunks per thread per stage ----
    const int fr = tid >> 2;          // 0..63
    const int fq = tid & 3;           // 16B chunk within 64B row
    const size_t oA0 = (size_t)(bm + fr) * K + fq * 8;
    const size_t oA1 = (size_t)(bm + fr + 64) * K + fq * 8;
    const size_t oW  = (size_t)(bn + fr) * K + fq * 8;
    const int sA0 = fr * SROW + fq * 16;        // 16B-aligned (80 = 5*16)
    const int sA1 = (fr + 64) * SROW + fq * 16;
    const int sW  = fr * SROW + fq * 16;

    auto issue = [&](int s, int k0) {
        char* b = sm + s * STAGE;
        cp16(b + sA0,                        Ah + oA0 + k0);
        cp16(b + sA1,                        Ah + oA1 + k0);
        cp16(b + A_BYTES + sA0,              Al + oA0 + k0);
        cp16(b + A_BYTES + sA1,              Al + oA1 + k0);
        cp16(b + 2 * A_BYTES + sW,           Wh + oW + k0);
        cp16(b + 2 * A_BYTES + W_BYTES + sW, Wl + oW + k0);
    };

    float acc[2][4][4];
#pragma unroll
    for (int i = 0; i < 2; i++)
#pragma unroll
        for (int j = 0; j < 4; j++)
#pragma unroll
            for (int e = 0; e < 4; e++) acc[i][j][e] = 0.f;

    const int kb0 = (lane & 3) * 4;   // byte offset of this thread's k pair
    const int gidr = lane >> 2;       // fragment row/col group

    auto compute = [&](int buf, int ksub) {
        const char* bA  = sm + buf * STAGE;
        const char* bAl = bA + A_BYTES;
        const char* bW  = bA + 2 * A_BYTES;
        const char* bWl = bW + W_BYTES;
        const int kb = ksub * 32 + kb0;

        unsigned bh[4][2], bl[4][2];
#pragma unroll
        for (int nf = 0; nf < 4; nf++) {
            const int off = (wn + nf * 8 + gidr) * SROW + kb;
            bh[nf][0] = *(const unsigned*)(bW + off);
            bh[nf][1] = *(const unsigned*)(bW + off + 16);
            bl[nf][0] = *(const unsigned*)(bWl + off);
            bl[nf][1] = *(const unsigned*)(bWl + off + 16);
        }
#pragma unroll
        for (int mf = 0; mf < 2; mf++) {
            const int off = (wm + mf * 16 + gidr) * SROW + kb;
            unsigned ah0 = *(const unsigned*)(bA + off);
            unsigned ah1 = *(const unsigned*)(bA + off + 8 * SROW);
            unsigned ah2 = *(const unsigned*)(bA + off + 16);
            unsigned ah3 = *(const unsigned*)(bA + off + 8 * SROW + 16);
            unsigned al0 = *(const unsigned*)(bAl + off);
            unsigned al1 = *(const unsigned*)(bAl + off + 8 * SROW);
            unsigned al2 = *(const unsigned*)(bAl + off + 16);
            unsigned al3 = *(const unsigned*)(bAl + off + 8 * SROW + 16);
#pragma unroll
            for (int nf = 0; nf < 4; nf++) {
                mma_bf16_(acc[mf][nf], ah0, ah1, ah2, ah3, bh[nf][0], bh[nf][1]);
                mma_bf16_(acc[mf][nf], ah0, ah1, ah2, ah3, bl[nf][0], bl[nf][1]);
                mma_bf16_(acc[mf][nf], al0, al1, al2, al3, bh[nf][0], bh[nf][1]);
            }
        }
    };

    // ---- 3-stage pipeline (compute first, then issue k+2) ----
    const int nk = K / 32;
    issue(0, 0);  CP_COMMIT();
    issue(1, 32); CP_COMMIT();

    int buf = 0;
    for (int k = 0; k < nk; k++) {
        CP_WAIT(1);
        __syncthreads();
        compute(buf, 0);
        compute(buf, 1);
        if (k + 2 < nk) issue((k + 2) % NSTAGES, (k + 2) * 32);
        CP_COMMIT();
        buf = (buf + 1) % NSTAGES;
    }

    // ---- epilogue ----
#pragma unroll
    for (int mf = 0; mf < 2; mf++) {
#pragma unroll
        for (int half = 0; half < 2; half++) {
            const int row = bm + wm + mf * 16 + gidr + half * 8;
            float mn = 0.f;
            int iv = 0;
            if (MODE == 3) { iv = invalid[row]; mn = maskn[row]; }
#pragma unroll
            for (int nf = 0; nf < 4; nf++) {
                const int col = bn + wn + nf * 8 + 2 * (lane & 3);
                float v0 = acc[mf][nf][half * 2 + 0];
                float v1 = acc[mf][nf][half * 2 + 1];
                if (MODE == 1) {
                    v0 = (v0 + bias[col]) * scale;
                    v1 = (v1 + bias[col + 1]) * scale;
                } else {
                    v0 += bias[col];
                    v1 += bias[col + 1];
                    const float* sr = src + (size_t)row * DMODEL + col;
                    v0 = iv ? sr[0] : fmaf(v0, mn, sr[0]);
                    v1 = iv ? sr[1] : fmaf(v1, mn, sr[1]);
                }
                *(float2*)&C[(size_t)row * ldc + col] = make_float2(v0, v1);
            }
        }
    }
}

// ---------------------------------------------------------------------------
// 128x128x8 SGEMM body (f32, FFMA2) for the small prep GEMMs, epilogue writes
// bf16 hi/lo pairs.  AT as before.
// ---------------------------------------------------------------------------
template <bool AT>
__device__ __forceinline__ void gemm_body_bf(
    const float* __restrict__ A, int lda,
    const float* __restrict__ W, int ldw,
    __nv_bfloat16* __restrict__ Chi, __nv_bfloat16* __restrict__ Clo,
    int ldc, int K, int bm, int bn,
    float (*As)[8][128], float (*Ws)[8][128])
{
    const int tid = threadIdx.x;
    const int arow = tid >> 1;
    const int acol = (tid & 1) << 2;
    const int wr = tid >> 5;
    const int wc = (tid & 31) << 2;
    const int ty = tid >> 4;
    const int tx = tid & 15;

    const float* Ap = AT ? (A + (size_t)wr * lda + bm + wc)
                         : (A + (size_t)(bm + arow) * lda + acol);
    const float* Wp = W + (size_t)wr * ldw + bn + wc;

    float4 av = *(const float4*)Ap;
    float4 wv = *(const float4*)Wp;
    if (AT) {
        *(float4*)&As[0][wr][wc] = av;
    } else {
        As[0][acol + 0][arow] = av.x; As[0][acol + 1][arow] = av.y;
        As[0][acol + 2][arow] = av.z; As[0][acol + 3][arow] = av.w;
    }
    *(float4*)&Ws[0][wr][wc] = wv;
    __syncthreads();

    unsigned long long acc2[8][4];
#pragma unroll
    for (int i = 0; i < 8; i++)
#pragma unroll
        for (int j = 0; j < 4; j++) acc2[i][j] = 0ull;

    int buf = 0;
    for (int k0 = 8; k0 <= K; k0 += 8) {
        const bool more = (k0 < K);
        if (more) {
            av = *(const float4*)(Ap + (AT ? (size_t)k0 * lda : (size_t)k0));
            wv = *(const float4*)(Wp + (size_t)k0 * ldw);
        }
#pragma unroll
        for (int k = 0; k < 8; k++) {
            float4 a0 = *(const float4*)&As[buf][k][ty * 8];
            float4 a1 = *(const float4*)&As[buf][k][ty * 8 + 4];
            float4 b0 = *(const float4*)&Ws[buf][k][tx * 8];
            float4 b1 = *(const float4*)&Ws[buf][k][tx * 8 + 4];
            unsigned long long rb2[4];
            rb2[0] = pk2(b0.x, b0.y); rb2[1] = pk2(b0.z, b0.w);
            rb2[2] = pk2(b1.x, b1.y); rb2[3] = pk2(b1.z, b1.w);
            float ra[8] = {a0.x, a0.y, a0.z, a0.w, a1.x, a1.y, a1.z, a1.w};
#pragma unroll
            for (int i = 0; i < 8; i++) {
                unsigned long long ra2 = pk2(ra[i], ra[i]);
#pragma unroll
                for (int j = 0; j < 4; j++) FMA2(acc2[i][j], ra2, rb2[j]);
            }
        }
        if (more) {
            const int nb = buf ^ 1;
            if (AT) {
                *(float4*)&As[nb][wr][wc] = av;
            } else {
                As[nb][acol + 0][arow] = av.x; As[nb][acol + 1][arow] = av.y;
                As[nb][acol + 2][arow] = av.z; As[nb][acol + 3][arow] = av.w;
            }
            *(float4*)&Ws[nb][wr][wc] = wv;
            __syncthreads();
            buf = nb;
        }
    }

#pragma unroll
    for (int i = 0; i < 8; i++) {
        const int r = bm + ty * 8 + i;
#pragma unroll
        for (int j = 0; j < 4; j++) {
            float2 p = unpk2(acc2[i][j]);
            float vv[2] = {p.x, p.y};
#pragma unroll
            for (int e = 0; e < 2; e++) {
                const int c = bn + tx * 8 + j * 2 + e;
                __nv_bfloat16 hi = __float2bfloat16(vv[e]);
                __nv_bfloat16 lo = __float2bfloat16(vv[e] - __bfloat162float(hi));
                Chi[(size_t)r * ldc + c] = hi;
                Clo[(size_t)r * ldc + c] = lo;
            }
        }
    }
}

// ---------------------------------------------------------------------------
// Combined prep: one launch, 135 CTAs.
//   0..31 : Ncat hi/lo (TN, K=256)    32..63 : Mcat hi/lo (NN, K=256)
//  64..65 : rb   66..67 : vqb   68..69 : bc   70 : cqb
//  71..134: source -> bf16 hi/lo
// ---------------------------------------------------------------------------
__global__ __launch_bounds__(256) void prep_all(
    const float* __restrict__ source,
    const float* __restrict__ Wq, const float* __restrict__ bq,
    const float* __restrict__ Wk, const float* __restrict__ bk,
    const float* __restrict__ Wv, const float* __restrict__ bv,
    const float* __restrict__ Wout, const float* __restrict__ bout)
{
    __shared__ float As[2][8][128];
    __shared__ float Ws[2][8][128];
    const int bid = blockIdx.x;
    const int tid = threadIdx.x;

    if (bid < 32) {
        const int h = bid >> 4, t = bid & 15;
        gemm_body_bf<true>(
            Wk + (size_t)h * 256 * DMODEL, DMODEL,
            Wq + (size_t)h * 256 * DMODEL, DMODEL,
            g_Nh + (size_t)h * 512 * DMODEL, g_Nl + (size_t)h * 512 * DMODEL,
            DMODEL, 256, (t >> 2) * 128, (t & 3) * 128, As, Ws);
    } else if (bid < 64) {
        const int idx = bid - 32, h = idx >> 4, t = idx & 15;
        gemm_body_bf<false>(
            Wout + (size_t)h * 256, DMODEL,
            Wv + (size_t)h * 256 * DMODEL, DMODEL,
            g_Mh + (size_t)h * 512, g_Ml + (size_t)h * 512,
            1024, 256, (t >> 2) * 128, (t & 3) * 128, As, Ws);
    } else if (bid < 66) {               // rb[h*512+g] = sum_j bq_h[j]*Wk_h[j,g]
        const int h = bid - 64;
        for (int cc = tid; cc < 512; cc += 256) {
            float acc = 0.f;
#pragma unroll 4
            for (int j = 0; j < 256; j++)
                acc = fmaf(bq[h * 256 + j], Wk[(size_t)(h * 256 + j) * 512 + cc], acc);
            g_rb[h * 512 + cc] = acc;
        }
    } else if (bid < 68) {               // vqb[h*512+k] = sum_j bk_h[j]*Wq_h[j,k]
        const int h = bid - 66;
        for (int cc = tid; cc < 512; cc += 256) {
            float acc = 0.f;
#pragma unroll 4
            for (int j = 0; j < 256; j++)
                acc = fmaf(bk[h * 256 + j], Wq[(size_t)(h * 256 + j) * 512 + cc], acc);
            g_vqb[h * 512 + cc] = acc;
        }
    } else if (bid < 70) {               // bc[j] = Wout[j,:].bv + bout[j]
        const int warp = tid >> 5, lane = tid & 31;
        const int base = (bid - 68) * 256;
        for (int i = 0; i < 32; i++) {
            const int j = base + warp * 32 + i;
            float s = 0.f;
            for (int c = lane; c < 512; c += 32)
                s = fmaf(Wout[(size_t)j * 512 + c], bv[c], s);
#pragma unroll
            for (int o = 16; o; o >>= 1) s += __shfl_xor_sync(0xffffffffu, s, o);
            if (lane == 0) g_bc[j] = s + bout[j];
        }
    } else if (bid == 70) {              // cqb[h] = bq_h . bk_h
        const int warp = tid >> 5, lane = tid & 31;
        if (warp < 2) {
            float s = 0.f;
            for (int j = lane; j < 256; j += 32)
                s = fmaf(bq[warp * 256 + j], bk[warp * 256 + j], s);
#pragma unroll
            for (int o = 16; o; o >>= 1) s += __shfl_xor_sync(0xffffffffu, s, o);
            if (lane == 0) g_cqb[warp] = s;
        }
    } else {                             // source -> bf16 hi/lo
        const int sb = bid - 71;         // 0..63
        const float4* sp = (const float4*)source;
        uint2* hOut = (uint2*)g_Sh;
        uint2* lOut = (uint2*)g_Sl;
#pragma unroll 4
        for (int i = 0; i < 32; i++) {
            const int idx = sb * 8192 + i * 256 + tid;
            float4 v = sp[idx];
            __nv_bfloat16 h0 = __float2bfloat16(v.x);
            __nv_bfloat16 h1 = __float2bfloat16(v.y);
            __nv_bfloat16 h2 = __float2bfloat16(v.z);
            __nv_bfloat16 h3 = __float2bfloat16(v.w);
            __nv_bfloat16 l0 = __float2bfloat16(v.x - __bfloat162float(h0));
            __nv_bfloat16 l1 = __float2bfloat16(v.y - __bfloat162float(h1));
            __nv_bfloat16 l2 = __float2bfloat16(v.z - __bfloat162float(h2));
            __nv_bfloat16 l3 = __float2bfloat16(v.w - __bfloat162float(h3));
            hOut[idx] = make_uint2(pack_bf2(h0, h1), pack_bf2(h2, h3));
            lOut[idx] = make_uint2(pack_bf2(l0, l1), pack_bf2(l2, l3));
        }
    }
}

// ---------------------------------------------------------------------------
// Per-row attention: qb, scores = r.gene + qb, mask (+slot-0 fix), softmax,
// attn_weight (head-mean), u = sum_s w*gene (written as bf16 hi/lo).
// One block per b, 256 threads.  gene + r staged via cp.async; the qb dot,
// mask load and invalid-fix execute while the 68 KB copy is in flight.
// ---------------------------------------------------------------------------
__global__ __launch_bounds__(256) void attn_kernel(
    const float* __restrict__ gene,
    const unsigned int* __restrict__ mask,
    const float* __restrict__ source,
    float* __restrict__ aw_out)
{
    extern __shared__ float dsm[];
    float* sg = dsm;            // [32*512] gene block
    float* rs = dsm + 16384;    // [1024] r row
    __shared__ float sc[64];
    __shared__ float wgt[64];
    __shared__ float qbs[2];
    __shared__ int mk[32];

    const int b = blockIdx.x;
    const int tid = threadIdx.x;
    const int warp = tid >> 5;
    const int lane = tid & 31;
    const float* gb = gene + (size_t)b * (SNEIGH * DMODEL);

    // async-stage gene block (64KB) + r row (4KB) into smem
    {
        const float4* gp = (const float4*)gb;
        float4* sp = (float4*)sg;
#pragma unroll
        for (int i = 0; i < 16; i++) cp16(sp + tid + i * 256, gp + tid + i * 256);
        cp16((float4*)rs + tid, (const float4*)(g_r + (size_t)b * 1024) + tid);
        CP_COMMIT();
    }
    if (tid < 32) mk[tid] = (mask[b * 32 + tid] != 0u) ? 1 : 0;

    // qb[h] = s*(source[b].vqb_h + cqb_h)  (warps 2,3) — overlaps cp.async
    if (warp == 2 || warp == 3) {
        const int h = warp - 2;
        const float* sr = source + (size_t)b * DMODEL;
        const float* vq = g_vqb + h * 512;
        float s = 0.f;
#pragma unroll
        for (int k = lane; k < 512; k += 32) s = fmaf(sr[k], vq[k], s);
#pragma unroll
        for (int o = 16; o; o >>= 1) s += __shfl_xor_sync(0xffffffffu, s, o);
        if (lane == 0) qbs[h] = QSCALE * (s + g_cqb[h]);
    }
    __syncthreads();

    if (warp == 0) {
        unsigned ball = __ballot_sync(0xffffffffu, mk[lane] != 0);
        if (lane == 0) {
            int inv = (ball == 0xffffffffu);
            g_inv[b] = inv;
            if (inv) mk[0] = 0;   // torch in-place fix: unmask slot 0
        }
    }
    CP_WAIT(0);
    __syncthreads();

    // scores: 64 (h,s) pairs; each warp does 8 full-warp dot-512s (smem only)
    for (int p = warp; p < 64; p += 8) {
        const int h = p >> 5, s = p & 31;
        const float* gr = sg + s * DMODEL;
        const float* rr = rs + h * 512;
        float sum = 0.f;
#pragma unroll
        for (int k = lane; k < 512; k += 32) sum = fmaf(rr[k], gr[k], sum);
#pragma unroll
        for (int o = 16; o; o >>= 1) sum += __shfl_xor_sync(0xffffffffu, sum, o);
        if (lane == 0) sc[p] = sum + qbs[h];
    }
    __syncthreads();

    // softmax per head (warps 0,1; lane = s)
    if (warp < 2) {
        float v = mk[lane] ? -INFINITY : sc[warp * 32 + lane];
        float mx = v;
#pragma unroll
        for (int o = 16; o; o >>= 1) mx = fmaxf(mx, __shfl_xor_sync(0xffffffffu, mx, o));
        float e = __expf(v - mx);
        float ssum = e;
#pragma unroll
        for (int o = 16; o; o >>= 1) ssum += __shfl_xor_sync(0xffffffffu, ssum, o);
        wgt[warp * 32 + lane] = e / ssum;
    }
    __syncthreads();

    if (tid < 32) aw_out[(size_t)b * 32 + tid] = 0.5f * (wgt[tid] + wgt[32 + tid]);

    // u[b,h,:] = sum_s w[h,s] * gene[b,s,:]  (from smem), write bf16 hi/lo
    const int g = tid;  // 0..255
    float a00 = 0.f, a01 = 0.f, a10 = 0.f, a11 = 0.f;
#pragma unroll 8
    for (int s = 0; s < 32; s++) {
        const float w0 = wgt[s];
        const float w1 = wgt[32 + s];
        const float gv0 = sg[s * DMODEL + g];
        const float gv1 = sg[s * DMODEL + g + 256];
        a00 = fmaf(w0, gv0, a00);
        a01 = fmaf(w0, gv1, a01);
        a10 = fmaf(w1, gv0, a10);
        a11 = fmaf(w1, gv1, a11);
    }
    __nv_bfloat16* uh = g_Uh + (size_t)b * 1024;
    __nv_bfloat16* ul = g_Ul + (size_t)b * 1024;
    float uv[4] = {a00, a01, a10, a11};
#pragma unroll
    for (int e = 0; e < 4; e++) {
        __nv_bfloat16 hi = __float2bfloat16(uv[e]);
        __nv_bfloat16 lo = __float2bfloat16(uv[e] - __bfloat162float(hi));
        uh[e * 256 + g] = hi;
        ul[e * 256 + g] = lo;
    }
}

// ---------------------------------------------------------------------------
extern "C" void kernel_launch(void* const* d_in, const int* in_sizes, int n_in,
                              void* d_out, int out_size)
{
    const float* source = (const float*)d_in[0];
    const float* gene   = (const float*)d_in[1];
    const unsigned int* mask = (const unsigned int*)d_in[2];
    const float* mask_n = (const float*)d_in[3];
    const float* Wq = (const float*)d_in[4];
    const float* bq = (const float*)d_in[5];
    const float* Wk = (const float*)d_in[6];
    const float* bk = (const float*)d_in[7];
    const float* Wv = (const float*)d_in[8];
    const float* bv = (const float*)d_in[9];
    const float* Wout = (const float*)d_in[10];
    const float* bout = (const float*)d_in[11];

    const int B = in_sizes[0] / DMODEL;   // 4096

    float* out = (float*)d_out;                         // [B,512]
    float* aw  = (float*)d_out + (size_t)B * DMODEL;    // [B,32]

    __nv_bfloat16 *Nh, *Nl, *Mh, *Ml, *Sh, *Sl, *Uh, *Ul;
    cudaGetSymbolAddress((void**)&Nh, g_Nh);  cudaGetSymbolAddress((void**)&Nl, g_Nl);
    cudaGetSymbolAddress((void**)&Mh, g_Mh);  cudaGetSymbolAddress((void**)&Ml, g_Ml);
    cudaGetSymbolAddress((void**)&Sh, g_Sh);  cudaGetSymbolAddress((void**)&Sl, g_Sl);
    cudaGetSymbolAddress((void**)&Uh, g_Uh);  cudaGetSymbolAddress((void**)&Ul, g_Ul);
    float* rbg; cudaGetSymbolAddress((void**)&rbg, g_rb);
    float* bcg; cudaGetSymbolAddress((void**)&bcg, g_bc);
    float* rg;  cudaGetSymbolAddress((void**)&rg, g_r);
    int*   ivg; cudaGetSymbolAddress((void**)&ivg, g_inv);

    static bool attrs_set = false;
    if (!attrs_set) {
        cudaFuncSetAttribute(mma_gemm<1>, cudaFuncAttributeMaxDynamicSharedMemorySize, NSTAGES * STAGE);
        cudaFuncSetAttribute(mma_gemm<3>, cudaFuncAttributeMaxDynamicSharedMemorySize, NSTAGES * STAGE);
        cudaFuncSetAttribute(attn_kernel, cudaFuncAttributeMaxDynamicSharedMemorySize, 17408 * 4);
        attrs_set = true;
    }

    // P) fused weights (bf16 hi/lo) + bias vectors + source conversion
    prep_all<<<135, 256>>>(source, Wq, bq, Wk, bk, Wv, bv, Wout, bout);

    // 1) r = QSCALE * (source @ Ncat^T + rb)   [B,1024], K=512  (tensor cores)
    mma_gemm<1><<<dim3(1024 / 64, B / 128), 256, NSTAGES * STAGE>>>(
        Sh, Sl, Nh, Nl, rg, 1024, DMODEL,
        rbg, QSCALE, nullptr, nullptr, nullptr);

    // 2) per-row attention: qb, scores, mask fix, softmax, attn_weight, u
    attn_kernel<<<B, 256, 17408 * 4>>>(gene, mask, source, aw);

    // 3) out = invalid ? source : (u @ Mcat^T + bc) * mask_n + source  K=1024
    mma_gemm<3><<<dim3(DMODEL / 64, B / 128), 256, NSTAGES * STAGE>>>(
        Uh, Ul, Mh, Ml, out, DMODEL, 1024,
        bcg, 1.f, mask_n, ivg, source);
}

// round 17
// speedup vs baseline: 1.1451x; 1.0421x over previous
#include <cuda_runtime.h>
#include <cuda_bf16.h>
#include <math.h>

// Problem constants (fixed dataset): B=4096, S=32, d=512, g=512, H=2, hd=256
#define BMAX 4096
#define DMODEL 512
#define SNEIGH 32
#define QSCALE 0.0625f   // hd^-0.5

// Scratch (static device arrays; no allocation allowed)
__device__ __align__(16) __nv_bfloat16 g_Nh[1024 * 512];  // fused r-weights hi
__device__ __align__(16) __nv_bfloat16 g_Nl[1024 * 512];  // fused r-weights lo
__device__ __align__(16) __nv_bfloat16 g_Mh[512 * 1024];  // fused out-weights hi
__device__ __align__(16) __nv_bfloat16 g_Ml[512 * 1024];  // fused out-weights lo
__device__ __align__(16) __nv_bfloat16 g_Sh[BMAX * DMODEL];  // source hi
__device__ __align__(16) __nv_bfloat16 g_Sl[BMAX * DMODEL];  // source lo
__device__ __align__(16) __nv_bfloat16 g_Uh[BMAX * 1024];    // u hi
__device__ __align__(16) __nv_bfloat16 g_Ul[BMAX * 1024];    // u lo
__device__ float g_rb[1024];          // bq_h @ Wk_h
__device__ float g_vqb[1024];         // Wq_h^T @ bk_h
__device__ float g_cqb[2];            // bq_h . bk_h
__device__ float g_bc[512];           // Wout @ bv + bout
__device__ float g_r[BMAX * 1024];    // r[b,h,:]
__device__ int   g_inv[BMAX];         // all-neighbors-padded flag

// ---- packed f32x2 helpers (for the small prep GEMM) ----
__device__ __forceinline__ unsigned long long pk2(float lo, float hi) {
    unsigned long long r;
    asm("mov.b64 %0, {%1, %2};" : "=l"(r) : "f"(lo), "f"(hi));
    return r;
}
__device__ __forceinline__ float2 unpk2(unsigned long long v) {
    float2 r;
    asm("mov.b64 {%0, %1}, %2;" : "=f"(r.x), "=f"(r.y) : "l"(v));
    return r;
}
#define FMA2(d, a, b) asm("fma.rn.f32x2 %0, %1, %2, %0;" : "+l"(d) : "l"(a), "l"(b))

__device__ __forceinline__ unsigned pack_bf2(__nv_bfloat16 a, __nv_bfloat16 b) {
    return ((unsigned)__bfloat16_as_ushort(b) << 16) | __bfloat16_as_ushort(a);
}

// ---- cp.async helpers ----
__device__ __forceinline__ void cp16(void* dst, const void* src) {
    unsigned d = (unsigned)__cvta_generic_to_shared(dst);
    asm volatile("cp.async.cg.shared.global [%0], [%1], 16;\n" :: "r"(d), "l"(src));
}
#define CP_COMMIT() asm volatile("cp.async.commit_group;\n")
#define CP_WAIT(n)  asm volatile("cp.async.wait_group %0;\n" :: "n"(n))

// ===========================================================================
// bf16 split-compensated tensor-core GEMM.
//   C[M,N] = A[M,K] @ W[N,K]^T  with A = Ah+Al, W = Wh+Wl (bf16 hi/lo pairs)
//   computed as Ah*Wh + Ah*Wl + Al*Wh (fp32 accum).
// CTA tile 128x64, 8 warps (4x2), warp tile 32x32, k-step 32,
// 3-stage cp.async pipeline, 2 CTAs/SM.  (R11 mainloop — proven fastest.)
// MODE 1: C = (acc + bias[c]) * scale                       (f32 out, ldc)
// MODE 3: C = invalid[r] ? src : (acc+bias[c])*maskn[r]+src (src ld=512)
// Smem per stage: Ah/Al 128x80B + Wh/Wl 64x80B = 30720 B;  3 stages = 92160 B
// ===========================================================================
#define SROW 80          // smem row stride in bytes (32 bf16 + 8 pad)
#define A_BYTES 10240    // 128 * 80
#define W_BYTES 5120     // 64 * 80
#define STAGE 30720      // 2*A_BYTES + 2*W_BYTES
#define NSTAGES 3

__device__ __forceinline__ void mma_bf16_(float* c,
    unsigned a0, unsigned a1, unsigned a2, unsigned a3,
    unsigned b0, unsigned b1)
{
    asm volatile(
        "mma.sync.aligned.m16n8k16.row.col.f32.bf16.bf16.f32 "
        "{%0,%1,%2,%3}, {%4,%5,%6,%7}, {%8,%9}, {%0,%1,%2,%3};\n"
        : "+f"(c[0]), "+f"(c[1]), "+f"(c[2]), "+f"(c[3])
        : "r"(a0), "r"(a1), "r"(a2), "r"(a3), "r"(b0), "r"(b1));
}

template <int MODE>
__global__ __launch_bounds__(256, 2) void mma_gemm(
    const __nv_bfloat16* __restrict__ Ah, const __nv_bfloat16* __restrict__ Al,
    const __nv_bfloat16* __restrict__ Wh, const __nv_bfloat16* __restrict__ Wl,
    float* __restrict__ C, int ldc, int K,
    const float* __restrict__ bias, float scale,
    const float* __restrict__ maskn,
    const int* __restrict__ invalid,
    const float* __restrict__ src)
{
    extern __shared__ char sm[];
    const int tid = threadIdx.x;
    const int wid = tid >> 5;
    const int lane = tid & 31;
    const int bm = blockIdx.y * 128;
    const int bn = blockIdx.x * 64;
    const int wm = (wid >> 1) * 32;   // 0,32,64,96
    const int wn = (wid & 1) * 32;    // 0,32

    // ---- cp.async fetch mapping: 6 x 16B chunks per thread per stage ----
    const int fr = tid >> 2;          // 0..63
    const int fq = tid & 3;           // 16B chunk within 64B row
    const size_t oA0 = (size_t)(bm + fr) * K + fq * 8;
    const size_t oA1 = (size_t)(bm + fr + 64) * K + fq * 8;
    const size_t oW  = (size_t)(bn + fr) * K + fq * 8;
    const int sA0 = fr * SROW + fq * 16;        // 16B-aligned (80 = 5*16)
    const int sA1 = (fr + 64) * SROW + fq * 16;
    const int sW  = fr * SROW + fq * 16;

    auto issue = [&](int s, int k0) {
        char* b = sm + s * STAGE;
        cp16(b + sA0,                        Ah + oA0 + k0);
        cp16(b + sA1,                        Ah + oA1 + k0);
        cp16(b + A_BYTES + sA0,              Al + oA0 + k0);
        cp16(b + A_BYTES + sA1,              Al + oA1 + k0);
        cp16(b + 2 * A_BYTES + sW,           Wh + oW + k0);
        cp16(b + 2 * A_BYTES + W_BYTES + sW, Wl + oW + k0);
    };

    float acc[2][4][4];
#pragma unroll
    for (int i = 0; i < 2; i++)
#pragma unroll
        for (int j = 0; j < 4; j++)
#pragma unroll
            for (int e = 0; e < 4; e++) acc[i][j][e] = 0.f;

    const int kb0 = (lane & 3) * 4;   // byte offset of this thread's k pair
    const int gidr = lane >> 2;       // fragment row/col group

    auto compute = [&](int buf, int ksub) {
        const char* bA  = sm + buf * STAGE;
        const char* bAl = bA + A_BYTES;
        const char* bW  = bA + 2 * A_BYTES;
        const char* bWl = bW + W_BYTES;
        const int kb = ksub * 32 + kb0;

        unsigned bh[4][2], bl[4][2];
#pragma unroll
        for (int nf = 0; nf < 4; nf++) {
            const int off = (wn + nf * 8 + gidr) * SROW + kb;
            bh[nf][0] = *(const unsigned*)(bW + off);
            bh[nf][1] = *(const unsigned*)(bW + off + 16);
            bl[nf][0] = *(const unsigned*)(bWl + off);
            bl[nf][1] = *(const unsigned*)(bWl + off + 16);
        }
#pragma unroll
        for (int mf = 0; mf < 2; mf++) {
            const int off = (wm + mf * 16 + gidr) * SROW + kb;
            unsigned ah0 = *(const unsigned*)(bA + off);
            unsigned ah1 = *(const unsigned*)(bA + off + 8 * SROW);
            unsigned ah2 = *(const unsigned*)(bA + off + 16);
            unsigned ah3 = *(const unsigned*)(bA + off + 8 * SROW + 16);
            unsigned al0 = *(const unsigned*)(bAl + off);
            unsigned al1 = *(const unsigned*)(bAl + off + 8 * SROW);
            unsigned al2 = *(const unsigned*)(bAl + off + 16);
            unsigned al3 = *(const unsigned*)(bAl + off + 8 * SROW + 16);
#pragma unroll
            for (int nf = 0; nf < 4; nf++) {
                mma_bf16_(acc[mf][nf], ah0, ah1, ah2, ah3, bh[nf][0], bh[nf][1]);
                mma_bf16_(acc[mf][nf], ah0, ah1, ah2, ah3, bl[nf][0], bl[nf][1]);
                mma_bf16_(acc[mf][nf], al0, al1, al2, al3, bh[nf][0], bh[nf][1]);
            }
        }
    };

    // ---- 3-stage pipeline (compute first, then issue k+2) ----
    const int nk = K / 32;
    issue(0, 0);  CP_COMMIT();
    issue(1, 32); CP_COMMIT();

    int buf = 0;
    for (int k = 0; k < nk; k++) {
        CP_WAIT(1);
        __syncthreads();
        compute(buf, 0);
        compute(buf, 1);
        if (k + 2 < nk) issue((k + 2) % NSTAGES, (k + 2) * 32);
        CP_COMMIT();
        buf = (buf + 1) % NSTAGES;
    }

    // ---- epilogue ----
#pragma unroll
    for (int mf = 0; mf < 2; mf++) {
#pragma unroll
        for (int half = 0; half < 2; half++) {
            const int row = bm + wm + mf * 16 + gidr + half * 8;
            float mn = 0.f;
            int iv = 0;
            if (MODE == 3) { iv = invalid[row]; mn = maskn[row]; }
#pragma unroll
            for (int nf = 0; nf < 4; nf++) {
                const int col = bn + wn + nf * 8 + 2 * (lane & 3);
                float v0 = acc[mf][nf][half * 2 + 0];
                float v1 = acc[mf][nf][half * 2 + 1];
                if (MODE == 1) {
                    v0 = (v0 + bias[col]) * scale;
                    v1 = (v1 + bias[col + 1]) * scale;
                } else {
                    v0 += bias[col];
                    v1 += bias[col + 1];
                    const float* sr = src + (size_t)row * DMODEL + col;
                    v0 = iv ? sr[0] : fmaf(v0, mn, sr[0]);
                    v1 = iv ? sr[1] : fmaf(v1, mn, sr[1]);
                }
                *(float2*)&C[(size_t)row * ldc + col] = make_float2(v0, v1);
            }
        }
    }
}

// ---------------------------------------------------------------------------
// 128x128x8 SGEMM body (f32, FFMA2) for the small prep GEMMs, epilogue writes
// bf16 hi/lo pairs.  AT as before.
// ---------------------------------------------------------------------------
template <bool AT>
__device__ __forceinline__ void gemm_body_bf(
    const float* __restrict__ A, int lda,
    const float* __restrict__ W, int ldw,
    __nv_bfloat16* __restrict__ Chi, __nv_bfloat16* __restrict__ Clo,
    int ldc, int K, int bm, int bn,
    float (*As)[8][128], float (*Ws)[8][128])
{
    const int tid = threadIdx.x;
    const int arow = tid >> 1;
    const int acol = (tid & 1) << 2;
    const int wr = tid >> 5;
    const int wc = (tid & 31) << 2;
    const int ty = tid >> 4;
    const int tx = tid & 15;

    const float* Ap = AT ? (A + (size_t)wr * lda + bm + wc)
                         : (A + (size_t)(bm + arow) * lda + acol);
    const float* Wp = W + (size_t)wr * ldw + bn + wc;

    float4 av = *(const float4*)Ap;
    float4 wv = *(const float4*)Wp;
    if (AT) {
        *(float4*)&As[0][wr][wc] = av;
    } else {
        As[0][acol + 0][arow] = av.x; As[0][acol + 1][arow] = av.y;
        As[0][acol + 2][arow] = av.z; As[0][acol + 3][arow] = av.w;
    }
    *(float4*)&Ws[0][wr][wc] = wv;
    __syncthreads();

    unsigned long long acc2[8][4];
#pragma unroll
    for (int i = 0; i < 8; i++)
#pragma unroll
        for (int j = 0; j < 4; j++) acc2[i][j] = 0ull;

    int buf = 0;
    for (int k0 = 8; k0 <= K; k0 += 8) {
        const bool more = (k0 < K);
        if (more) {
            av = *(const float4*)(Ap + (AT ? (size_t)k0 * lda : (size_t)k0));
            wv = *(const float4*)(Wp + (size_t)k0 * ldw);
        }
#pragma unroll
        for (int k = 0; k < 8; k++) {
            float4 a0 = *(const float4*)&As[buf][k][ty * 8];
            float4 a1 = *(const float4*)&As[buf][k][ty * 8 + 4];
            float4 b0 = *(const float4*)&Ws[buf][k][tx * 8];
            float4 b1 = *(const float4*)&Ws[buf][k][tx * 8 + 4];
            unsigned long long rb2[4];
            rb2[0] = pk2(b0.x, b0.y); rb2[1] = pk2(b0.z, b0.w);
            rb2[2] = pk2(b1.x, b1.y); rb2[3] = pk2(b1.z, b1.w);
            float ra[8] = {a0.x, a0.y, a0.z, a0.w, a1.x, a1.y, a1.z, a1.w};
#pragma unroll
            for (int i = 0; i < 8; i++) {
                unsigned long long ra2 = pk2(ra[i], ra[i]);
#pragma unroll
                for (int j = 0; j < 4; j++) FMA2(acc2[i][j], ra2, rb2[j]);
            }
        }
        if (more) {
            const int nb = buf ^ 1;
            if (AT) {
                *(float4*)&As[nb][wr][wc] = av;
            } else {
                As[nb][acol + 0][arow] = av.x; As[nb][acol + 1][arow] = av.y;
                As[nb][acol + 2][arow] = av.z; As[nb][acol + 3][arow] = av.w;
            }
            *(float4*)&Ws[nb][wr][wc] = wv;
            __syncthreads();
            buf = nb;
        }
    }

#pragma unroll
    for (int i = 0; i < 8; i++) {
        const int r = bm + ty * 8 + i;
#pragma unroll
        for (int j = 0; j < 4; j++) {
            float2 p = unpk2(acc2[i][j]);
            float vv[2] = {p.x, p.y};
#pragma unroll
            for (int e = 0; e < 2; e++) {
                const int c = bn + tx * 8 + j * 2 + e;
                __nv_bfloat16 hi = __float2bfloat16(vv[e]);
                __nv_bfloat16 lo = __float2bfloat16(vv[e] - __bfloat162float(hi));
                Chi[(size_t)r * ldc + c] = hi;
                Clo[(size_t)r * ldc + c] = lo;
            }
        }
    }
}

// ---------------------------------------------------------------------------
// Combined prep: one launch, 135 CTAs.
//   0..31 : Ncat hi/lo (TN, K=256)    32..63 : Mcat hi/lo (NN, K=256)
//  64..65 : rb   66..67 : vqb   68..69 : bc   70 : cqb
//  71..134: source -> bf16 hi/lo
// ---------------------------------------------------------------------------
__global__ __launch_bounds__(256) void prep_all(
    const float* __restrict__ source,
    const float* __restrict__ Wq, const float* __restrict__ bq,
    const float* __restrict__ Wk, const float* __restrict__ bk,
    const float* __restrict__ Wv, const float* __restrict__ bv,
    const float* __restrict__ Wout, const float* __restrict__ bout)
{
    __shared__ float As[2][8][128];
    __shared__ float Ws[2][8][128];
    const int bid = blockIdx.x;
    const int tid = threadIdx.x;

    if (bid < 32) {
        const int h = bid >> 4, t = bid & 15;
        gemm_body_bf<true>(
            Wk + (size_t)h * 256 * DMODEL, DMODEL,
            Wq + (size_t)h * 256 * DMODEL, DMODEL,
            g_Nh + (size_t)h * 512 * DMODEL, g_Nl + (size_t)h * 512 * DMODEL,
            DMODEL, 256, (t >> 2) * 128, (t & 3) * 128, As, Ws);
    } else if (bid < 64) {
        const int idx = bid - 32, h = idx >> 4, t = idx & 15;
        gemm_body_bf<false>(
            Wout + (size_t)h * 256, DMODEL,
            Wv + (size_t)h * 256 * DMODEL, DMODEL,
            g_Mh + (size_t)h * 512, g_Ml + (size_t)h * 512,
            1024, 256, (t >> 2) * 128, (t & 3) * 128, As, Ws);
    } else if (bid < 66) {               // rb[h*512+g] = sum_j bq_h[j]*Wk_h[j,g]
        const int h = bid - 64;
        for (int cc = tid; cc < 512; cc += 256) {
            float acc = 0.f;
#pragma unroll 4
            for (int j = 0; j < 256; j++)
                acc = fmaf(bq[h * 256 + j], Wk[(size_t)(h * 256 + j) * 512 + cc], acc);
            g_rb[h * 512 + cc] = acc;
        }
    } else if (bid < 68) {               // vqb[h*512+k] = sum_j bk_h[j]*Wq_h[j,k]
        const int h = bid - 66;
        for (int cc = tid; cc < 512; cc += 256) {
            float acc = 0.f;
#pragma unroll 4
            for (int j = 0; j < 256; j++)
                acc = fmaf(bk[h * 256 + j], Wq[(size_t)(h * 256 + j) * 512 + cc], acc);
            g_vqb[h * 512 + cc] = acc;
        }
    } else if (bid < 70) {               // bc[j] = Wout[j,:].bv + bout[j]
        const int warp = tid >> 5, lane = tid & 31;
        const int base = (bid - 68) * 256;
        for (int i = 0; i < 32; i++) {
            const int j = base + warp * 32 + i;
            float s = 0.f;
            for (int c = lane; c < 512; c += 32)
                s = fmaf(Wout[(size_t)j * 512 + c], bv[c], s);
#pragma unroll
            for (int o = 16; o; o >>= 1) s += __shfl_xor_sync(0xffffffffu, s, o);
            if (lane == 0) g_bc[j] = s + bout[j];
        }
    } else if (bid == 70) {              // cqb[h] = bq_h . bk_h
        const int warp = tid >> 5, lane = tid & 31;
        if (warp < 2) {
            float s = 0.f;
            for (int j = lane; j < 256; j += 32)
                s = fmaf(bq[warp * 256 + j], bk[warp * 256 + j], s);
#pragma unroll
            for (int o = 16; o; o >>= 1) s += __shfl_xor_sync(0xffffffffu, s, o);
            if (lane == 0) g_cqb[warp] = s;
        }
    } else {                             // source -> bf16 hi/lo
        const int sb = bid - 71;         // 0..63
        const float4* sp = (const float4*)source;
        uint2* hOut = (uint2*)g_Sh;
        uint2* lOut = (uint2*)g_Sl;
#pragma unroll 4
        for (int i = 0; i < 32; i++) {
            const int idx = sb * 8192 + i * 256 + tid;
            float4 v = sp[idx];
            __nv_bfloat16 h0 = __float2bfloat16(v.x);
            __nv_bfloat16 h1 = __float2bfloat16(v.y);
            __nv_bfloat16 h2 = __float2bfloat16(v.z);
            __nv_bfloat16 h3 = __float2bfloat16(v.w);
            __nv_bfloat16 l0 = __float2bfloat16(v.x - __bfloat162float(h0));
            __nv_bfloat16 l1 = __float2bfloat16(v.y - __bfloat162float(h1));
            __nv_bfloat16 l2 = __float2bfloat16(v.z - __bfloat162float(h2));
            __nv_bfloat16 l3 = __float2bfloat16(v.w - __bfloat162float(h3));
            hOut[idx] = make_uint2(pack_bf2(h0, h1), pack_bf2(h2, h3));
            lOut[idx] = make_uint2(pack_bf2(l0, l1), pack_bf2(l2, l3));
        }
    }
}

// ---------------------------------------------------------------------------
// Per-row attention: qb, scores = r.gene + qb, mask (+slot-0 fix), softmax,
// attn_weight (head-mean), u = sum_s w*gene (written as bf16 hi/lo).
// One block per b, 256 threads.  gene + r staged via cp.async overlapped with
// the qb dot.  Score pass: each warp preloads BOTH r rows into registers and
// handles 4 s-slots, reading each gene row from smem exactly ONCE (both heads
// share the read) — smem crossbar traffic for scores drops 256KB -> 96KB/CTA.
// ---------------------------------------------------------------------------
__global__ __launch_bounds__(256) void attn_kernel(
    const float* __restrict__ gene,
    const unsigned int* __restrict__ mask,
    const float* __restrict__ source,
    float* __restrict__ aw_out)
{
    extern __shared__ float dsm[];
    float* sg = dsm;            // [32*512] gene block
    float* rs = dsm + 16384;    // [1024] r row
    __shared__ float sc[64];
    __shared__ float wgt[64];
    __shared__ float qbs[2];
    __shared__ int mk[32];

    const int b = blockIdx.x;
    const int tid = threadIdx.x;
    const int warp = tid >> 5;
    const int lane = tid & 31;
    const float* gb = gene + (size_t)b * (SNEIGH * DMODEL);

    // async-stage gene block (64KB) + r row (4KB) into smem
    {
        const float4* gp = (const float4*)gb;
        float4* sp = (float4*)sg;
#pragma unroll
        for (int i = 0; i < 16; i++) cp16(sp + tid + i * 256, gp + tid + i * 256);
        cp16((float4*)rs + tid, (const float4*)(g_r + (size_t)b * 1024) + tid);
        CP_COMMIT();
    }
    if (tid < 32) mk[tid] = (mask[b * 32 + tid] != 0u) ? 1 : 0;

    // qb[h] = s*(source[b].vqb_h + cqb_h)  (warps 2,3) — overlaps cp.async
    if (warp == 2 || warp == 3) {
        const int h = warp - 2;
        const float* sr = source + (size_t)b * DMODEL;
        const float* vq = g_vqb + h * 512;
        float s = 0.f;
#pragma unroll
        for (int k = lane; k < 512; k += 32) s = fmaf(sr[k], vq[k], s);
#pragma unroll
        for (int o = 16; o; o >>= 1) s += __shfl_xor_sync(0xffffffffu, s, o);
        if (lane == 0) qbs[h] = QSCALE * (s + g_cqb[h]);
    }
    __syncthreads();

    if (warp == 0) {
        unsigned ball = __ballot_sync(0xffffffffu, mk[lane] != 0);
        if (lane == 0) {
            int inv = (ball == 0xffffffffu);
            g_inv[b] = inv;
            if (inv) mk[0] = 0;   // torch in-place fix: unmask slot 0
        }
    }
    CP_WAIT(0);
    __syncthreads();

    // ---- scores: warp w handles s in [w*4, w*4+4), BOTH heads per gene read.
    // Preload both r rows into registers (conflict-free: lanes contiguous).
    {
        float r0reg[16], r1reg[16];
#pragma unroll
        for (int i = 0; i < 16; i++) {
            r0reg[i] = rs[i * 32 + lane];
            r1reg[i] = rs[512 + i * 32 + lane];
        }
        const float qb0 = qbs[0], qb1 = qbs[1];
#pragma unroll
        for (int si = 0; si < 4; si++) {
            const int s = warp * 4 + si;
            const float* gr = sg + s * DMODEL;
            float s0 = 0.f, s1 = 0.f;
#pragma unroll
            for (int i = 0; i < 16; i++) {
                const float g = gr[i * 32 + lane];
                s0 = fmaf(r0reg[i], g, s0);
                s1 = fmaf(r1reg[i], g, s1);
            }
#pragma unroll
            for (int o = 16; o; o >>= 1) {
                s0 += __shfl_xor_sync(0xffffffffu, s0, o);
                s1 += __shfl_xor_sync(0xffffffffu, s1, o);
            }
            if (lane == 0) {
                sc[s] = s0 + qb0;
                sc[32 + s] = s1 + qb1;
            }
        }
    }
    __syncthreads();

    // softmax per head (warps 0,1; lane = s)
    if (warp < 2) {
        float v = mk[lane] ? -INFINITY : sc[warp * 32 + lane];
        float mx = v;
#pragma unroll
        for (int o = 16; o; o >>= 1) mx = fmaxf(mx, __shfl_xor_sync(0xffffffffu, mx, o));
        float e = __expf(v - mx);
        float ssum = e;
#pragma unroll
        for (int o = 16; o; o >>= 1) ssum += __shfl_xor_sync(0xffffffffu, ssum, o);
        wgt[warp * 32 + lane] = e / ssum;
    }
    __syncthreads();

    if (tid < 32) aw_out[(size_t)b * 32 + tid] = 0.5f * (wgt[tid] + wgt[32 + tid]);

    // u[b,h,:] = sum_s w[h,s] * gene[b,s,:]  (from smem), write bf16 hi/lo
    const int g = tid;  // 0..255
    float a00 = 0.f, a01 = 0.f, a10 = 0.f, a11 = 0.f;
#pragma unroll 8
    for (int s = 0; s < 32; s++) {
        const float w0 = wgt[s];
        const float w1 = wgt[32 + s];
        const float gv0 = sg[s * DMODEL + g];
        const float gv1 = sg[s * DMODEL + g + 256];
        a00 = fmaf(w0, gv0, a00);
        a01 = fmaf(w0, gv1, a01);
        a10 = fmaf(w1, gv0, a10);
        a11 = fmaf(w1, gv1, a11);
    }
    __nv_bfloat16* uh = g_Uh + (size_t)b * 1024;
    __nv_bfloat16* ul = g_Ul + (size_t)b * 1024;
    float uv[4] = {a00, a01, a10, a11};
#pragma unroll
    for (int e = 0; e < 4; e++) {
        __nv_bfloat16 hi = __float2bfloat16(uv[e]);
        __nv_bfloat16 lo = __float2bfloat16(uv[e] - __bfloat162float(hi));
        uh[e * 256 + g] = hi;
        ul[e * 256 + g] = lo;
    }
}

// ---------------------------------------------------------------------------
extern "C" void kernel_launch(void* const* d_in, const int* in_sizes, int n_in,
                              void* d_out, int out_size)
{
    const float* source = (const float*)d_in[0];
    const float* gene   = (const float*)d_in[1];
    const unsigned int* mask = (const unsigned int*)d_in[2];
    const float* mask_n = (const float*)d_in[3];
    const float* Wq = (const float*)d_in[4];
    const float* bq = (const float*)d_in[5];
    const float* Wk = (const float*)d_in[6];
    const float* bk = (const float*)d_in[7];
    const float* Wv = (const float*)d_in[8];
    const float* bv = (const float*)d_in[9];
    const float* Wout = (const float*)d_in[10];
    const float* bout = (const float*)d_in[11];

    const int B = in_sizes[0] / DMODEL;   // 4096

    float* out = (float*)d_out;                         // [B,512]
    float* aw  = (float*)d_out + (size_t)B * DMODEL;    // [B,32]

    __nv_bfloat16 *Nh, *Nl, *Mh, *Ml, *Sh, *Sl, *Uh, *Ul;
    cudaGetSymbolAddress((void**)&Nh, g_Nh);  cudaGetSymbolAddress((void**)&Nl, g_Nl);
    cudaGetSymbolAddress((void**)&Mh, g_Mh);  cudaGetSymbolAddress((void**)&Ml, g_Ml);
    cudaGetSymbolAddress((void**)&Sh, g_Sh);  cudaGetSymbolAddress((void**)&Sl, g_Sl);
    cudaGetSymbolAddress((void**)&Uh, g_Uh);  cudaGetSymbolAddress((void**)&Ul, g_Ul);
    float* rbg; cudaGetSymbolAddress((void**)&rbg, g_rb);
    float* bcg; cudaGetSymbolAddress((void**)&bcg, g_bc);
    float* rg;  cudaGetSymbolAddress((void**)&rg, g_r);
    int*   ivg; cudaGetSymbolAddress((void**)&ivg, g_inv);

    static bool attrs_set = false;
    if (!attrs_set) {
        cudaFuncSetAttribute(mma_gemm<1>, cudaFuncAttributeMaxDynamicSharedMemorySize, NSTAGES * STAGE);
        cudaFuncSetAttribute(mma_gemm<3>, cudaFuncAttributeMaxDynamicSharedMemorySize, NSTAGES * STAGE);
        cudaFuncSetAttribute(attn_kernel, cudaFuncAttributeMaxDynamicSharedMemorySize, 17408 * 4);
        attrs_set = true;
    }

    // P) fused weights (bf16 hi/lo) + bias vectors + source conversion
    prep_all<<<135, 256>>>(source, Wq, bq, Wk, bk, Wv, bv, Wout, bout);

    // 1) r = QSCALE * (source @ Ncat^T + rb)   [B,1024], K=512  (tensor cores)
    mma_gemm<1><<<dim3(1024 / 64, B / 128), 256, NSTAGES * STAGE>>>(
        Sh, Sl, Nh, Nl, rg, 1024, DMODEL,
        rbg, QSCALE, nullptr, nullptr, nullptr);

    // 2) per-row attention: qb, scores, mask fix, softmax, attn_weight, u
    attn_kernel<<<B, 256, 17408 * 4>>>(gene, mask, source, aw);

    // 3) out = invalid ? source : (u @ Mcat^T + bc) * mask_n + source  K=1024
    mma_gemm<3><<<dim3(DMODEL / 64, B / 128), 256, NSTAGES * STAGE>>>(
        Uh, Ul, Mh, Ml, out, DMODEL, 1024,
        bcg, 1.f, mask_n, ivg, source);
}